// round 4
// baseline (speedup 1.0000x reference)
#include <cuda_runtime.h>

// Problem constants
static constexpr int B_   = 4;
static constexpr int W_   = 12;
static constexpr int N_   = 1024;
static constexpr int FIN_ = 32;
static constexpr int FOUT_= 32;
static constexpr int H_   = 256;
static constexpr int BW_  = B_ * W_;        // 48
static constexpr int D_   = N_ * FOUT_;     // 32768
static constexpr int KC_  = 128;            // split-K chunks for gates GEMM (k=256 each)
static constexpr int KQ_  = 4;              // split-K for gcn GEMM (k=256 each)

// ---------------- packed f32x2 helpers ----------------
#define FMA2(acc, a, b) asm("fma.rn.f32x2 %0, %1, %2, %0;" : "+l"(acc) : "l"(a), "l"(b))
#define PACK2(d, f)     asm("mov.b64 %0, {%1, %1};" : "=l"(d) : "f"(f))
#define UNPACK2(lo, hi, d) asm("mov.b64 {%0, %1}, %2;" : "=f"(lo), "=f"(hi) : "l"(d))

// ---------------- scratch (static device globals; no allocation) ----------------
__device__ float g_deg[BW_ * N_];
__device__ float g_P[(size_t)BW_ * N_ * FOUT_];
__device__ float g_xpart[(size_t)KQ_ * BW_ * N_ * FOUT_];   // gcn split-K partials
__device__ float g_X[(size_t)BW_ * D_];                     // [wb = w*B+b][D]
__device__ float g_part[(size_t)KC_ * BW_ * 4 * H_];        // gates split-K partials
__device__ float g_gates[BW_ * 4 * H_];
__device__ float g_h[2][B_ * H_];
__device__ float g_out[B_ * D_];
__device__ float g_s1[B_ * N_];
__device__ float g_s2[B_ * N_];
__device__ int   g_barrier;

// ---------------- K1: degree  d = (1 + rowsum(in_shots))^-1/2 ----------------
__global__ void k_deg(const float* __restrict__ shots) {
    int row  = blockIdx.x * 8 + (threadIdx.x >> 5);
    int lane = threadIdx.x & 31;
    const float4* p = (const float4*)(shots + (size_t)row * N_);
    float s = 0.f;
#pragma unroll
    for (int i = 0; i < 8; i++) {
        float4 v = p[lane + 32 * i];
        s += v.x + v.y + v.z + v.w;
    }
#pragma unroll
    for (int o = 16; o; o >>= 1) s += __shfl_xor_sync(0xffffffffu, s, o);
    if (lane == 0) g_deg[row] = 1.0f / sqrtf(1.0f + s);
}

// ---------------- K2: P[m,o] = d[m] * (node[m,:] @ gcn_w[w])[o] ----------------
__global__ void k_P(const float* __restrict__ node, const float* __restrict__ gcn_w) {
    __shared__ float gw[FIN_ * FOUT_];
    int r0 = blockIdx.x * 8;
    int w  = (r0 / N_) % W_;            // row index is bw-major: bw = b*W + w
    for (int i = threadIdx.x; i < FIN_ * FOUT_; i += 256) gw[i] = gcn_w[(size_t)w * FIN_ * FOUT_ + i];
    __syncthreads();
    int warp = threadIdx.x >> 5, lane = threadIdx.x & 31;
    int r = r0 + warp;
    float nv = node[(size_t)r * FIN_ + lane];
    float acc = 0.f;
#pragma unroll
    for (int f = 0; f < FIN_; f++) {
        float x = __shfl_sync(0xffffffffu, nv, f);
        acc += x * gw[f * FOUT_ + lane];
    }
    g_P[(size_t)r * FOUT_ + lane] = g_deg[r] * acc;
}

// ---------------- K3: xpart[kq] = shots[n, kq-chunk] @ P[kq-chunk, :] ----------
// 128 threads (4 warps), tile 256 rows x 32 cols, thread tile 8x8 (f32x2),
// register-prefetch pipelined staging. Grid = (48 bw * 4 row-tiles, 4 kq).
static constexpr int AS2_ = 284;   // A_shT row stride (floats), max f=283
__global__ __launch_bounds__(128) void k_gcn(const float* __restrict__ shots) {
    __shared__ __align__(16) float AT[16 * AS2_];  // [kk][f(row)]
    __shared__ __align__(16) float PS[16 * 32];    // [kk][col]
    int bw = blockIdx.x >> 2;
    int n0 = (blockIdx.x & 3) << 8;      // * 256
    int kq = blockIdx.y;
    int t = threadIdx.x;
    int tx = t & 3;          // col group (8 cols each)
    int ty = t >> 2;         // row group (8 rows each), 0..31
    const float* Abase = shots + (size_t)bw * N_ * N_;
    const float* Pbase = g_P + (size_t)bw * N_ * FOUT_;

    unsigned long long acc[4][8];
#pragma unroll
    for (int i = 0; i < 4; i++)
#pragma unroll
        for (int j = 0; j < 8; j++) acc[i][j] = 0ull;

    const int r8 = ty * 8;
    const int fr = r8 + ((r8 >> 5) << 2);   // bank-spread row index

    float4 pa[8];
    float4 pp;
    const int kbase = kq * 256;

    // prefetch stage 0
    {
#pragma unroll
        for (int i = 0; i < 8; i++) {
            int idx = t + 128 * i;
            int rr = idx >> 2, q = idx & 3;
            pa[i] = *(const float4*)(Abase + (size_t)(n0 + rr) * N_ + kbase + 4 * q);
        }
        int kk = t >> 3, c = t & 7;
        pp = *(const float4*)(Pbase + (size_t)(kbase + kk) * 32 + 4 * c);
    }

    for (int s = 0; s < 16; s++) {
        __syncthreads();   // buffer free (previous compute done)
        // STS staged regs
#pragma unroll
        for (int i = 0; i < 8; i++) {
            int idx = t + 128 * i;
            int rr = idx >> 2, q = idx & 3;
            int f = rr + ((rr >> 5) << 2);
            AT[(4 * q + 0) * AS2_ + f] = pa[i].x;
            AT[(4 * q + 1) * AS2_ + f] = pa[i].y;
            AT[(4 * q + 2) * AS2_ + f] = pa[i].z;
            AT[(4 * q + 3) * AS2_ + f] = pa[i].w;
        }
        {
            int kk = t >> 3, c = t & 7;
            *(float4*)&PS[kk * 32 + 4 * c] = pp;
        }
        __syncthreads();   // buffer ready
        // prefetch next stage (overlaps compute)
        if (s < 15) {
            int k0 = kbase + (s + 1) * 16;
#pragma unroll
            for (int i = 0; i < 8; i++) {
                int idx = t + 128 * i;
                int rr = idx >> 2, q = idx & 3;
                pa[i] = *(const float4*)(Abase + (size_t)(n0 + rr) * N_ + k0 + 4 * q);
            }
            int kk = t >> 3, c = t & 7;
            pp = *(const float4*)(Pbase + (size_t)(k0 + kk) * 32 + 4 * c);
        }
#pragma unroll 4
        for (int kk = 0; kk < 16; kk++) {
            ulonglong2 aA = *(const ulonglong2*)&AT[kk * AS2_ + fr];
            ulonglong2 aB = *(const ulonglong2*)&AT[kk * AS2_ + fr + 4];
            float4 p0 = *(const float4*)&PS[kk * 32 + tx * 8];
            float4 p1 = *(const float4*)&PS[kk * 32 + tx * 8 + 4];
            unsigned long long ap[4];
            ap[0] = aA.x; ap[1] = aA.y; ap[2] = aB.x; ap[3] = aB.y;
            unsigned long long bb[8];
            PACK2(bb[0], p0.x); PACK2(bb[1], p0.y); PACK2(bb[2], p0.z); PACK2(bb[3], p0.w);
            PACK2(bb[4], p1.x); PACK2(bb[5], p1.y); PACK2(bb[6], p1.z); PACK2(bb[7], p1.w);
#pragma unroll
            for (int i = 0; i < 4; i++)
#pragma unroll
                for (int j = 0; j < 8; j++) FMA2(acc[i][j], ap[i], bb[j]);
        }
    }

    // epilogue: write raw partials (reorder/deg/P-add done in k_xfin)
    float* Xp = g_xpart + (size_t)kq * BW_ * N_ * FOUT_ + (size_t)bw * N_ * FOUT_;
#pragma unroll
    for (int i = 0; i < 4; i++) {
        int ne = n0 + r8 + 2 * i;
        float lo[8], hi[8];
#pragma unroll
        for (int j = 0; j < 8; j++) UNPACK2(lo[j], hi[j], acc[i][j]);
        float4 o0 = {lo[0], lo[1], lo[2], lo[3]};
        float4 o1 = {lo[4], lo[5], lo[6], lo[7]};
        float4 o2 = {hi[0], hi[1], hi[2], hi[3]};
        float4 o3 = {hi[4], hi[5], hi[6], hi[7]};
        *(float4*)(Xp + (size_t)ne * 32 + tx * 8) = o0;
        *(float4*)(Xp + (size_t)ne * 32 + tx * 8 + 4) = o1;
        *(float4*)(Xp + (size_t)(ne + 1) * 32 + tx * 8) = o2;
        *(float4*)(Xp + (size_t)(ne + 1) * 32 + tx * 8 + 4) = o3;
    }
}

// ---------------- K3f: X[n,o] = d[n]*(sum_kq xpart + P[n,o]), time-major --------
__global__ void k_xfin(void) {
    int i4 = blockIdx.x * 256 + threadIdx.x;         // float4 index
    size_t e = (size_t)i4 * 4;
    int bw = (int)(e >> 15);                         // / 32768
    int r  = (int)(e & 32767);
    int n  = r >> 5;
    float4 s = *(const float4*)(g_P + e);
#pragma unroll
    for (int kq = 0; kq < KQ_; kq++) {
        float4 p = *(const float4*)(g_xpart + (size_t)kq * BW_ * N_ * FOUT_ + e);
        s.x += p.x; s.y += p.y; s.z += p.z; s.w += p.w;
    }
    float d = g_deg[bw * N_ + n];
    s.x *= d; s.y *= d; s.z *= d; s.w *= d;
    int w = bw % W_, b = bw / W_;
    *(float4*)(g_X + (size_t)(w * B_ + b) * D_ + r) = s;
}

// ---------------- K4: gates_x = X @ w_ih^T  (deep split-K, prefetch pipelined) --
static constexpr int XS_ = 52;    // X_shT stride
static constexpr int WS_ = 132;   // W_shT stride
__global__ __launch_bounds__(192) void k_gates(const float* __restrict__ w_ih) {
    __shared__ __align__(16) float XT[32 * XS_];   // [kk][wb]
    __shared__ __align__(16) float WT[32 * WS_];   // [kk][g]
    int g0 = blockIdx.x * 128;
    int kc = blockIdx.y;
    int kbase = kc * 256;
    int t = threadIdx.x;
    int warp = t >> 5, gl = t & 31;
    int wb0 = warp * 8;

    unsigned long long acc[4][4];
#pragma unroll
    for (int i = 0; i < 4; i++)
#pragma unroll
        for (int j = 0; j < 4; j++) acc[i][j] = 0ull;

    float4 pw[6];
    float4 px[2];

    // prefetch stage 0
    {
#pragma unroll
        for (int i = 0; i < 6; i++) {
            int idx = t + 192 * i;
            if (idx < 1024) {
                int g = idx >> 3, q = idx & 7;
                pw[i] = *(const float4*)(w_ih + (size_t)(g0 + g) * D_ + kbase + 4 * q);
            }
        }
#pragma unroll
        for (int i = 0; i < 2; i++) {
            int idx = t + 192 * i;
            int wb = idx >> 3, q = idx & 7;
            px[i] = *(const float4*)(g_X + (size_t)wb * D_ + kbase + 4 * q);
        }
    }

    for (int s = 0; s < 8; s++) {
        __syncthreads();
        // STS staged regs
#pragma unroll
        for (int i = 0; i < 6; i++) {
            int idx = t + 192 * i;
            if (idx < 1024) {
                int g = idx >> 3, q = idx & 7;
                WT[(4 * q + 0) * WS_ + g] = pw[i].x;
                WT[(4 * q + 1) * WS_ + g] = pw[i].y;
                WT[(4 * q + 2) * WS_ + g] = pw[i].z;
                WT[(4 * q + 3) * WS_ + g] = pw[i].w;
            }
        }
#pragma unroll
        for (int i = 0; i < 2; i++) {
            int idx = t + 192 * i;
            int wb = idx >> 3, q = idx & 7;
            XT[(4 * q + 0) * XS_ + wb] = px[i].x;
            XT[(4 * q + 1) * XS_ + wb] = px[i].y;
            XT[(4 * q + 2) * XS_ + wb] = px[i].z;
            XT[(4 * q + 3) * XS_ + wb] = px[i].w;
        }
        __syncthreads();
        // prefetch next stage (overlaps compute)
        if (s < 7) {
            int k0 = kbase + (s + 1) * 32;
#pragma unroll
            for (int i = 0; i < 6; i++) {
                int idx = t + 192 * i;
                if (idx < 1024) {
                    int g = idx >> 3, q = idx & 7;
                    pw[i] = *(const float4*)(w_ih + (size_t)(g0 + g) * D_ + k0 + 4 * q);
                }
            }
#pragma unroll
            for (int i = 0; i < 2; i++) {
                int idx = t + 192 * i;
                int wb = idx >> 3, q = idx & 7;
                px[i] = *(const float4*)(g_X + (size_t)wb * D_ + k0 + 4 * q);
            }
        }
#pragma unroll 4
        for (int kk = 0; kk < 32; kk++) {
            ulonglong2 xA = *(const ulonglong2*)&XT[kk * XS_ + wb0];       // broadcast
            ulonglong2 xB = *(const ulonglong2*)&XT[kk * XS_ + wb0 + 4];
            float4 wv = *(const float4*)&WT[kk * WS_ + gl * 4];
            unsigned long long ap[4];
            ap[0] = xA.x; ap[1] = xA.y; ap[2] = xB.x; ap[3] = xB.y;
            unsigned long long b2[4];
            PACK2(b2[0], wv.x); PACK2(b2[1], wv.y); PACK2(b2[2], wv.z); PACK2(b2[3], wv.w);
#pragma unroll
            for (int i = 0; i < 4; i++)
#pragma unroll
                for (int j = 0; j < 4; j++) FMA2(acc[i][j], ap[i], b2[j]);
        }
    }
    // epilogue -> split-K partials
#pragma unroll
    for (int i = 0; i < 4; i++) {
#pragma unroll
        for (int j = 0; j < 4; j++) {
            float lo, hi;
            UNPACK2(lo, hi, acc[i][j]);
            int gcol = g0 + gl * 4 + j;
            g_part[((size_t)kc * BW_ + wb0 + 2 * i) * 1024 + gcol] = lo;
            g_part[((size_t)kc * BW_ + wb0 + 2 * i + 1) * 1024 + gcol] = hi;
        }
    }
}

// ---------------- K4r: reduce split-K + biases ----------------------------------
__global__ void k_greduce(const float* __restrict__ b_ih, const float* __restrict__ b_hh) {
    int i = blockIdx.x * 256 + threadIdx.x;   // 0..49151
    int g = i & 1023;
    float s = b_ih[g] + b_hh[g];
#pragma unroll 8
    for (int kc = 0; kc < KC_; kc++) s += g_part[(size_t)kc * BW_ * 1024 + i];
    g_gates[i] = s;
}

// ---------------- init h0 + barrier ----------------------------------------------
__global__ void k_init() {
    int t = threadIdx.x;
    g_h[0][t] = 0.f;
    if (t == 0) g_barrier = 0;
}

// ---------------- K5: fused 12-step LSTM (persistent, grid spin-barrier) --------
// grid (8, B) x 32 threads; thread = hidden unit j; 32 blocks total (all resident)
__global__ void k_lstm(const float* __restrict__ w_hh) {
    __shared__ __align__(16) float hsh[H_];
    int b = blockIdx.y;
    int j = blockIdx.x * 32 + threadIdx.x;
    const float4* wr[4];
#pragma unroll
    for (int r = 0; r < 4; r++) wr[r] = (const float4*)(w_hh + (size_t)(r * H_ + j) * H_);
    float cc = 0.f;

    for (int w = 0; w < W_; w++) {
        int parity = w & 1;
        const float* h = g_h[parity] + b * H_;
        for (int i = threadIdx.x; i < H_; i += 32) hsh[i] = h[i];
        __syncwarp();

        const float* gx = g_gates + ((size_t)(w * B_ + b)) * 4 * H_;
        float acc[4] = {gx[j], gx[H_ + j], gx[2 * H_ + j], gx[3 * H_ + j]};
        const float4* h4 = (const float4*)hsh;
#pragma unroll 8
        for (int k = 0; k < H_ / 4; k++) {
            float4 hv = h4[k];
#pragma unroll
            for (int r = 0; r < 4; r++) {
                float4 wv = wr[r][k];
                acc[r] += wv.x * hv.x + wv.y * hv.y + wv.z * hv.z + wv.w * hv.w;
            }
        }
        float ig = 1.0f / (1.0f + expf(-acc[0]));
        float fg = 1.0f / (1.0f + expf(-acc[1]));
        float gg = tanhf(acc[2]);
        float og = 1.0f / (1.0f + expf(-acc[3]));
        cc = fg * cc + ig * gg;
        g_h[parity ^ 1][b * H_ + j] = og * tanhf(cc);

        // grid barrier: all 32 blocks must finish step w before step w+1
        __syncwarp();
        if (threadIdx.x == 0) {
            int target = 32 * (w + 1);
            asm volatile("red.release.gpu.global.add.s32 [%0], 1;" :: "l"(&g_barrier));
            int v;
            do {
                asm volatile("ld.acquire.gpu.global.s32 %0, [%1];" : "=r"(v) : "l"(&g_barrier));
            } while (v < target);
        }
        __syncwarp();
    }
}

// ---------------- K6: out[b, r] = hn[b,:]·f1_w[r,:] + f1_b[r] -------------------
__global__ void k_out(const float* __restrict__ f1_w, const float* __restrict__ f1_b) {
    __shared__ __align__(16) float hsh[B_ * H_];
    for (int i = threadIdx.x; i < B_ * H_; i += 256) hsh[i] = g_h[0][i];  // 12 steps -> parity 0
    __syncthreads();
    int warp = threadIdx.x >> 5, lane = threadIdx.x & 31;
    int r = blockIdx.x * 8 + warp;
    const float4* Wr = (const float4*)(f1_w + (size_t)r * H_);
    float a[B_] = {0.f, 0.f, 0.f, 0.f};
#pragma unroll
    for (int t = 0; t < 2; t++) {
        int idx = lane + 32 * t;
        float4 wv = Wr[idx];
#pragma unroll
        for (int b = 0; b < B_; b++) {
            float4 hv = *(const float4*)&hsh[b * H_ + idx * 4];
            a[b] += wv.x * hv.x + wv.y * hv.y + wv.z * hv.z + wv.w * hv.w;
        }
    }
#pragma unroll
    for (int b = 0; b < B_; b++) {
#pragma unroll
        for (int o = 16; o; o >>= 1) a[b] += __shfl_xor_sync(0xffffffffu, a[b], o);
    }
    if (lane == 0) {
        float bb = f1_b[r];
#pragma unroll
        for (int b = 0; b < B_; b++) g_out[(size_t)b * D_ + r] = a[b] + bb;
    }
}

// ---------------- K6c: s1[b,n], s2[b,n] -----------------------------------------
__global__ void k_s(const float* __restrict__ f2_w) {
    int idx = blockIdx.x * 256 + threadIdx.x;  // 0..4095 : b*N + n
    const float4* v4 = (const float4*)(g_out + (size_t)idx * FOUT_);
    const float4* w1 = (const float4*)(f2_w);
    const float4* w2 = (const float4*)(f2_w + FOUT_);
    float s1 = 0.f, s2 = 0.f;
#pragma unroll
    for (int t = 0; t < 8; t++) {
        float4 v = v4[t], a = w1[t], b = w2[t];
        s1 += v.x * a.x + v.y * a.y + v.z * a.z + v.w * a.w;
        s2 += v.x * b.x + v.y * b.y + v.z * b.z + v.w * b.w;
    }
    g_s1[idx] = s1;
    g_s2[idx] = s2;
}

// ---------------- K7: scores, keep mask, L1 row-normalize, write output ----------
__global__ void k_final(float* __restrict__ res, const float* __restrict__ f2_b) {
    __shared__ float s1s[N_], s2s[N_];
    __shared__ float wsum[8];
    __shared__ float total;
    int b = blockIdx.x >> 10;
    int i = blockIdx.x & 1023;
    for (int t = threadIdx.x; t < N_; t += 256) {
        s1s[t] = g_s1[b * N_ + t];
        s2s[t] = g_s2[b * N_ + t];
    }
    __syncthreads();
    float bias = f2_b[0];
    float s1i = s1s[i], s2i = s2s[i];
    float v[4];
    float asum = 0.f;
#pragma unroll
    for (int t = 0; t < 4; t++) {
        int j = threadIdx.x + t * 256;
        float sc = s1i + s2s[j] + bias;
        float st = s1s[j] + s2i + bias;
        float val;
        if (i == j) {
            val = sc;
        } else {
            bool keep = (i < j) ? (sc >= st && sc > 0.f) : (sc > st && sc >= 0.f);
            val = keep ? sc : 0.f;
        }
        v[t] = val;
        asum += fabsf(val);
    }
    int warp = threadIdx.x >> 5, lane = threadIdx.x & 31;
#pragma unroll
    for (int o = 16; o; o >>= 1) asum += __shfl_xor_sync(0xffffffffu, asum, o);
    if (lane == 0) wsum[warp] = asum;
    __syncthreads();
    if (threadIdx.x == 0) {
        float s = 0.f;
#pragma unroll
        for (int k = 0; k < 8; k++) s += wsum[k];
        total = s;
    }
    __syncthreads();
    float inv = 1.0f / fmaxf(total, 1e-12f);
    float* row = res + ((size_t)b * N_ + i) * N_;
#pragma unroll
    for (int t = 0; t < 4; t++) row[threadIdx.x + t * 256] = v[t] * inv;
}

// =================================================================================
extern "C" void kernel_launch(void* const* d_in, const int* in_sizes, int n_in,
                              void* d_out, int out_size) {
    const float* shots = (const float*)d_in[0];
    const float* node  = (const float*)d_in[1];
    // d_in[2] = 'a' (unused by reference)
    const float* gcn_w = (const float*)d_in[3];
    const float* w_ih  = (const float*)d_in[4];
    const float* w_hh  = (const float*)d_in[5];
    const float* b_ih  = (const float*)d_in[6];
    const float* b_hh  = (const float*)d_in[7];
    const float* f1_w  = (const float*)d_in[8];
    const float* f1_b  = (const float*)d_in[9];
    const float* f2_w  = (const float*)d_in[10];
    const float* f2_b  = (const float*)d_in[11];
    float* res = (float*)d_out;

    k_deg<<<BW_ * N_ / 8, 256>>>(shots);
    k_P<<<BW_ * N_ / 8, 256>>>(node, gcn_w);
    k_gcn<<<dim3(BW_ * 4, KQ_), 128>>>(shots);
    k_xfin<<<BW_ * N_ * FOUT_ / 4 / 256, 256>>>();
    k_gates<<<dim3(8, KC_), 192>>>(w_ih);
    k_greduce<<<BW_ * 4 * H_ / 256, 256>>>(b_ih, b_hh);
    k_init<<<1, B_ * H_>>>();
    k_lstm<<<dim3(8, B_), 32>>>(w_hh);
    k_out<<<D_ / 8, 256>>>(f1_w, f1_b);
    k_s<<<B_ * N_ / 256, 256>>>(f2_w);
    k_final<<<B_ * N_, 256>>>(res, f2_b);
}

// round 6
// speedup vs baseline: 1.1786x; 1.1786x over previous
#include <cuda_runtime.h>

// Problem constants
static constexpr int B_   = 4;
static constexpr int W_   = 12;
static constexpr int N_   = 1024;
static constexpr int FIN_ = 32;
static constexpr int FOUT_= 32;
static constexpr int H_   = 256;
static constexpr int BW_  = B_ * W_;        // 48
static constexpr int D_   = N_ * FOUT_;     // 32768
static constexpr int KC_  = 128;            // split-K chunks for gates GEMM (k=256 each)
static constexpr int KQ_  = 8;              // split-K for gcn GEMM (k=128 each)

// ---------------- packed f32x2 helpers ----------------
#define FMA2(acc, a, b) asm("fma.rn.f32x2 %0, %1, %2, %0;" : "+l"(acc) : "l"(a), "l"(b))
#define PACK2(d, f)     asm("mov.b64 %0, {%1, %1};" : "=l"(d) : "f"(f))
#define UNPACK2(lo, hi, d) asm("mov.b64 {%0, %1}, %2;" : "=f"(lo), "=f"(hi) : "l"(d))

// ---------------- scratch (static device globals; no allocation) ----------------
__device__ float g_deg[BW_ * N_];
__device__ float g_P[(size_t)BW_ * N_ * FOUT_];
__device__ float g_xpart[(size_t)KQ_ * BW_ * N_ * FOUT_];   // gcn split-K partials (50MB)
__device__ float g_X[(size_t)BW_ * D_];                     // [wb = w*B+b][D]
__device__ float g_part[(size_t)KC_ * BW_ * 4 * H_];        // gates split-K partials
__device__ float g_gates[BW_ * 4 * H_];
__device__ float g_h[2][B_ * H_];
__device__ float g_out[B_ * D_];
__device__ float g_s1[B_ * N_];
__device__ float g_s2[B_ * N_];
__device__ int   g_barrier;

// ---------------- init h0 + barrier (launched FIRST; independent) ----------------
__global__ void k_init() {
    int t = threadIdx.x;
    g_h[0][t] = 0.f;
    if (t == 0) g_barrier = 0;
}

// ---------------- K1: degree  d = (1 + rowsum(in_shots))^-1/2 ----------------
__global__ void k_deg(const float* __restrict__ shots) {
    int row  = blockIdx.x * 8 + (threadIdx.x >> 5);
    int lane = threadIdx.x & 31;
    const float4* p = (const float4*)(shots + (size_t)row * N_);
    float s = 0.f;
#pragma unroll
    for (int i = 0; i < 8; i++) {
        float4 v = p[lane + 32 * i];
        s += v.x + v.y + v.z + v.w;
    }
#pragma unroll
    for (int o = 16; o; o >>= 1) s += __shfl_xor_sync(0xffffffffu, s, o);
    if (lane == 0) g_deg[row] = 1.0f / sqrtf(1.0f + s);
}

// ---------------- K2: P[m,o] = d[m] * (node[m,:] @ gcn_w[w])[o] ----------------
__global__ void k_P(const float* __restrict__ node, const float* __restrict__ gcn_w) {
    __shared__ float gw[FIN_ * FOUT_];
    int r0 = blockIdx.x * 8;
    int w  = (r0 / N_) % W_;            // row index is bw-major: bw = b*W + w
    for (int i = threadIdx.x; i < FIN_ * FOUT_; i += 256) gw[i] = gcn_w[(size_t)w * FIN_ * FOUT_ + i];
    __syncthreads();
    int warp = threadIdx.x >> 5, lane = threadIdx.x & 31;
    int r = r0 + warp;
    float nv = node[(size_t)r * FIN_ + lane];
    float acc = 0.f;
#pragma unroll
    for (int f = 0; f < FIN_; f++) {
        float x = __shfl_sync(0xffffffffu, nv, f);
        acc += x * gw[f * FOUT_ + lane];
    }
    g_P[(size_t)r * FOUT_ + lane] = g_deg[r] * acc;
}

// ---------------- K3: xpart[kq] = shots[n, kq-chunk] @ P[kq-chunk, :] ----------
// (exact R3 structure) 64 threads, tile 128 rows x 32 cols, thread tile 8x8,
// f32x2 inner loop. Grid = (48 bw * 8 row-tiles, KQ_=8 k-chunks of 128).
static constexpr int AS_ = 292;   // A_shT row stride (floats)
__global__ __launch_bounds__(64) void k_gcn(const float* __restrict__ shots) {
    __shared__ __align__(16) float AT[16 * AS_];   // [kk][f(row)]
    __shared__ __align__(16) float PS[16 * 32];    // [kk][col]
    int bw = blockIdx.x >> 3;
    int n0 = (blockIdx.x & 7) << 7;      // * 128
    int kq = blockIdx.y;
    int t = threadIdx.x;
    int tx = t & 3;          // col group (8 cols each)
    int ty = t >> 2;         // row group (8 rows each), 0..15
    const float* Abase = shots + (size_t)bw * N_ * N_;
    const float* Pbase = g_P + (size_t)bw * N_ * FOUT_;

    unsigned long long acc[4][8];
#pragma unroll
    for (int i = 0; i < 4; i++)
#pragma unroll
        for (int j = 0; j < 8; j++) acc[i][j] = 0ull;

    const int r8 = ty * 8;
    const int fr = r8 + ((r8 >> 5) << 2);   // bank-spread row index

    for (int k0 = kq * 128; k0 < kq * 128 + 128; k0 += 16) {
        // stage A tile (128 rows x 16 k), transposed with swizzled row index
#pragma unroll
        for (int i = 0; i < 8; i++) {
            int idx = t + 64 * i;
            int rr = idx >> 2, q = idx & 3;
            float4 v = *(const float4*)(Abase + (size_t)(n0 + rr) * N_ + k0 + 4 * q);
            int f = rr + ((rr >> 5) << 2);
            AT[(4 * q + 0) * AS_ + f] = v.x;
            AT[(4 * q + 1) * AS_ + f] = v.y;
            AT[(4 * q + 2) * AS_ + f] = v.z;
            AT[(4 * q + 3) * AS_ + f] = v.w;
        }
        // stage P tile (16 k x 32 cols)
#pragma unroll
        for (int i = 0; i < 2; i++) {
            int idx = t + 64 * i;
            int kk = idx >> 3, c = idx & 7;
            *(float4*)&PS[kk * 32 + 4 * c] =
                *(const float4*)(Pbase + (size_t)(k0 + kk) * 32 + 4 * c);
        }
        __syncthreads();
#pragma unroll 4
        for (int kk = 0; kk < 16; kk++) {
            ulonglong2 aA = *(const ulonglong2*)&AT[kk * AS_ + fr];
            ulonglong2 aB = *(const ulonglong2*)&AT[kk * AS_ + fr + 4];
            float4 p0 = *(const float4*)&PS[kk * 32 + tx * 8];
            float4 p1 = *(const float4*)&PS[kk * 32 + tx * 8 + 4];
            unsigned long long ap[4];
            ap[0] = aA.x; ap[1] = aA.y; ap[2] = aB.x; ap[3] = aB.y;
            unsigned long long bb[8];
            PACK2(bb[0], p0.x); PACK2(bb[1], p0.y); PACK2(bb[2], p0.z); PACK2(bb[3], p0.w);
            PACK2(bb[4], p1.x); PACK2(bb[5], p1.y); PACK2(bb[6], p1.z); PACK2(bb[7], p1.w);
#pragma unroll
            for (int i = 0; i < 4; i++)
#pragma unroll
                for (int j = 0; j < 8; j++) FMA2(acc[i][j], ap[i], bb[j]);
        }
        __syncthreads();
    }

    // epilogue: write raw partials (reorder/deg/P-add done in k_xfin)
    float* Xp = g_xpart + (size_t)kq * BW_ * N_ * FOUT_ + (size_t)bw * N_ * FOUT_;
#pragma unroll
    for (int i = 0; i < 4; i++) {
        int ne = n0 + r8 + 2 * i;
        float lo[8], hi[8];
#pragma unroll
        for (int j = 0; j < 8; j++) UNPACK2(lo[j], hi[j], acc[i][j]);
        float4 o0 = {lo[0], lo[1], lo[2], lo[3]};
        float4 o1 = {lo[4], lo[5], lo[6], lo[7]};
        float4 o2 = {hi[0], hi[1], hi[2], hi[3]};
        float4 o3 = {hi[4], hi[5], hi[6], hi[7]};
        *(float4*)(Xp + (size_t)ne * 32 + tx * 8) = o0;
        *(float4*)(Xp + (size_t)ne * 32 + tx * 8 + 4) = o1;
        *(float4*)(Xp + (size_t)(ne + 1) * 32 + tx * 8) = o2;
        *(float4*)(Xp + (size_t)(ne + 1) * 32 + tx * 8 + 4) = o3;
    }
}

// ---------------- K3f: X[n,o] = d[n]*(sum_kq xpart + P[n,o]), time-major --------
__global__ void k_xfin(void) {
    int i4 = blockIdx.x * 256 + threadIdx.x;         // float4 index
    size_t e = (size_t)i4 * 4;
    int bw = (int)(e >> 15);                         // / 32768
    int r  = (int)(e & 32767);
    int n  = r >> 5;
    float4 s = *(const float4*)(g_P + e);
#pragma unroll
    for (int kq = 0; kq < KQ_; kq++) {
        float4 p = *(const float4*)(g_xpart + (size_t)kq * BW_ * N_ * FOUT_ + e);
        s.x += p.x; s.y += p.y; s.z += p.z; s.w += p.w;
    }
    float d = g_deg[bw * N_ + n];
    s.x *= d; s.y *= d; s.z *= d; s.w *= d;
    int w = bw % W_, b = bw / W_;
    *(float4*)(g_X + (size_t)(w * B_ + b) * D_ + r) = s;
}

// ---------------- K4: gates_x = X @ w_ih^T  (exact R3: deep split-K, f32x2) -----
static constexpr int XS_ = 52;    // X_shT stride
static constexpr int WS_ = 132;   // W_shT stride
__global__ __launch_bounds__(192) void k_gates(const float* __restrict__ w_ih) {
    __shared__ __align__(16) float XT[32 * XS_];   // [kk][wb]
    __shared__ __align__(16) float WT[32 * WS_];   // [kk][g]
    int g0 = blockIdx.x * 128;
    int kc = blockIdx.y;
    int k0base = kc * 256;
    int t = threadIdx.x;
    int warp = t >> 5, gl = t & 31;
    int wb0 = warp * 8;

    unsigned long long acc[4][4];
#pragma unroll
    for (int i = 0; i < 4; i++)
#pragma unroll
        for (int j = 0; j < 4; j++) acc[i][j] = 0ull;

    for (int s = 0; s < 8; s++) {
        int k0 = k0base + s * 32;
        // stage W: 128 g x 32 k, transposed
        for (int idx = t; idx < 1024; idx += 192) {
            int g = idx >> 3, q = idx & 7;
            float4 v = *(const float4*)(w_ih + (size_t)(g0 + g) * D_ + k0 + 4 * q);
            WT[(4 * q + 0) * WS_ + g] = v.x;
            WT[(4 * q + 1) * WS_ + g] = v.y;
            WT[(4 * q + 2) * WS_ + g] = v.z;
            WT[(4 * q + 3) * WS_ + g] = v.w;
        }
        // stage X: 48 wb x 32 k, transposed
        for (int idx = t; idx < 384; idx += 192) {
            int wb = idx >> 3, q = idx & 7;
            float4 v = *(const float4*)(g_X + (size_t)wb * D_ + k0 + 4 * q);
            XT[(4 * q + 0) * XS_ + wb] = v.x;
            XT[(4 * q + 1) * XS_ + wb] = v.y;
            XT[(4 * q + 2) * XS_ + wb] = v.z;
            XT[(4 * q + 3) * XS_ + wb] = v.w;
        }
        __syncthreads();
#pragma unroll 4
        for (int kk = 0; kk < 32; kk++) {
            ulonglong2 xA = *(const ulonglong2*)&XT[kk * XS_ + wb0];       // broadcast
            ulonglong2 xB = *(const ulonglong2*)&XT[kk * XS_ + wb0 + 4];
            float4 wv = *(const float4*)&WT[kk * WS_ + gl * 4];
            unsigned long long ap[4];
            ap[0] = xA.x; ap[1] = xA.y; ap[2] = xB.x; ap[3] = xB.y;
            unsigned long long b2[4];
            PACK2(b2[0], wv.x); PACK2(b2[1], wv.y); PACK2(b2[2], wv.z); PACK2(b2[3], wv.w);
#pragma unroll
            for (int i = 0; i < 4; i++)
#pragma unroll
                for (int j = 0; j < 4; j++) FMA2(acc[i][j], ap[i], b2[j]);
        }
        __syncthreads();
    }
    // epilogue -> split-K partials
#pragma unroll
    for (int i = 0; i < 4; i++) {
#pragma unroll
        for (int j = 0; j < 4; j++) {
            float lo, hi;
            UNPACK2(lo, hi, acc[i][j]);
            int gcol = g0 + gl * 4 + j;
            g_part[((size_t)kc * BW_ + wb0 + 2 * i) * 1024 + gcol] = lo;
            g_part[((size_t)kc * BW_ + wb0 + 2 * i + 1) * 1024 + gcol] = hi;
        }
    }
}

// ---------------- K4r: reduce split-K + biases ----------------------------------
__global__ void k_greduce(const float* __restrict__ b_ih, const float* __restrict__ b_hh) {
    int i = blockIdx.x * 256 + threadIdx.x;   // 0..49151
    int g = i & 1023;
    float s = b_ih[g] + b_hh[g];
#pragma unroll 8
    for (int kc = 0; kc < KC_; kc++) s += g_part[(size_t)kc * BW_ * 1024 + i];
    g_gates[i] = s;
}

// ---------------- K5: fused 12-step LSTM (persistent, grid spin-barrier) --------
// grid (8, B) x 32 threads; thread = hidden unit j; 32 blocks total (all resident)
__global__ void k_lstm(const float* __restrict__ w_hh) {
    __shared__ __align__(16) float hsh[H_];
    int b = blockIdx.y;
    int j = blockIdx.x * 32 + threadIdx.x;
    const float4* wr[4];
#pragma unroll
    for (int r = 0; r < 4; r++) wr[r] = (const float4*)(w_hh + (size_t)(r * H_ + j) * H_);
    float cc = 0.f;

    for (int w = 0; w < W_; w++) {
        int parity = w & 1;
        // cross-block data: bypass (incoherent) L1 with __ldcg
        const float4* hg = (const float4*)(g_h[parity] + b * H_);
#pragma unroll
        for (int i = 0; i < 2; i++) {
            int idx = threadIdx.x + 32 * i;       // float4 index 0..63
            ((float4*)hsh)[idx] = __ldcg(&hg[idx]);
        }
        __syncwarp();

        const float* gx = g_gates + ((size_t)(w * B_ + b)) * 4 * H_;
        float acc[4] = {gx[j], gx[H_ + j], gx[2 * H_ + j], gx[3 * H_ + j]};
        const float4* h4 = (const float4*)hsh;
#pragma unroll 8
        for (int k = 0; k < H_ / 4; k++) {
            float4 hv = h4[k];
#pragma unroll
            for (int r = 0; r < 4; r++) {
                float4 wv = wr[r][k];
                acc[r] += wv.x * hv.x + wv.y * hv.y + wv.z * hv.z + wv.w * hv.w;
            }
        }
        float ig = 1.0f / (1.0f + expf(-acc[0]));
        float fg = 1.0f / (1.0f + expf(-acc[1]));
        float gg = tanhf(acc[2]);
        float og = 1.0f / (1.0f + expf(-acc[3]));
        cc = fg * cc + ig * gg;
        // cross-block publish: write-through (STG.cg)
        float hv = og * tanhf(cc);
        asm volatile("st.global.cg.f32 [%0], %1;" :: "l"(&g_h[parity ^ 1][b * H_ + j]), "f"(hv));

        // grid barrier: all 32 blocks must finish step w before step w+1
        __syncwarp();
        if (threadIdx.x == 0) {
            int target = 32 * (w + 1);
            asm volatile("red.release.gpu.global.add.s32 [%0], 1;" :: "l"(&g_barrier));
            int v;
            do {
                asm volatile("ld.acquire.gpu.global.s32 %0, [%1];" : "=r"(v) : "l"(&g_barrier));
            } while (v < target);
        }
        __syncwarp();
    }
}

// ---------------- K6: out[b, r] = hn[b,:]·f1_w[r,:] + f1_b[r] -------------------
__global__ void k_out(const float* __restrict__ f1_w, const float* __restrict__ f1_b) {
    __shared__ __align__(16) float hsh[B_ * H_];
    for (int i = threadIdx.x; i < B_ * H_; i += 256) hsh[i] = g_h[0][i];  // 12 steps -> parity 0
    __syncthreads();
    int warp = threadIdx.x >> 5, lane = threadIdx.x & 31;
    int r = blockIdx.x * 8 + warp;
    const float4* Wr = (const float4*)(f1_w + (size_t)r * H_);
    float a[B_] = {0.f, 0.f, 0.f, 0.f};
#pragma unroll
    for (int t = 0; t < 2; t++) {
        int idx = lane + 32 * t;
        float4 wv = Wr[idx];
#pragma unroll
        for (int b = 0; b < B_; b++) {
            float4 hv = *(const float4*)&hsh[b * H_ + idx * 4];
            a[b] += wv.x * hv.x + wv.y * hv.y + wv.z * hv.z + wv.w * hv.w;
        }
    }
#pragma unroll
    for (int b = 0; b < B_; b++) {
#pragma unroll
        for (int o = 16; o; o >>= 1) a[b] += __shfl_xor_sync(0xffffffffu, a[b], o);
    }
    if (lane == 0) {
        float bb = f1_b[r];
#pragma unroll
        for (int b = 0; b < B_; b++) g_out[(size_t)b * D_ + r] = a[b] + bb;
    }
}

// ---------------- K6c: s1[b,n], s2[b,n] -----------------------------------------
__global__ void k_s(const float* __restrict__ f2_w) {
    int idx = blockIdx.x * 256 + threadIdx.x;  // 0..4095 : b*N + n
    const float4* v4 = (const float4*)(g_out + (size_t)idx * FOUT_);
    const float4* w1 = (const float4*)(f2_w);
    const float4* w2 = (const float4*)(f2_w + FOUT_);
    float s1 = 0.f, s2 = 0.f;
#pragma unroll
    for (int t = 0; t < 8; t++) {
        float4 v = v4[t], a = w1[t], b = w2[t];
        s1 += v.x * a.x + v.y * a.y + v.z * a.z + v.w * a.w;
        s2 += v.x * b.x + v.y * b.y + v.z * b.z + v.w * b.w;
    }
    g_s1[idx] = s1;
    g_s2[idx] = s2;
}

// ---------------- K7: scores, keep mask, L1 row-normalize, write output ----------
__global__ void k_final(float* __restrict__ res, const float* __restrict__ f2_b) {
    __shared__ float s1s[N_], s2s[N_];
    __shared__ float wsum[8];
    __shared__ float total;
    int b = blockIdx.x >> 10;
    int i = blockIdx.x & 1023;
    for (int t = threadIdx.x; t < N_; t += 256) {
        s1s[t] = g_s1[b * N_ + t];
        s2s[t] = g_s2[b * N_ + t];
    }
    __syncthreads();
    float bias = f2_b[0];
    float s1i = s1s[i], s2i = s2s[i];
    float v[4];
    float asum = 0.f;
#pragma unroll
    for (int t = 0; t < 4; t++) {
        int j = threadIdx.x + t * 256;
        float sc = s1i + s2s[j] + bias;
        float st = s1s[j] + s2i + bias;
        float val;
        if (i == j) {
            val = sc;
        } else {
            bool keep = (i < j) ? (sc >= st && sc > 0.f) : (sc > st && sc >= 0.f);
            val = keep ? sc : 0.f;
        }
        v[t] = val;
        asum += fabsf(val);
    }
    int warp = threadIdx.x >> 5, lane = threadIdx.x & 31;
#pragma unroll
    for (int o = 16; o; o >>= 1) asum += __shfl_xor_sync(0xffffffffu, asum, o);
    if (lane == 0) wsum[warp] = asum;
    __syncthreads();
    if (threadIdx.x == 0) {
        float s = 0.f;
#pragma unroll
        for (int k = 0; k < 8; k++) s += wsum[k];
        total = s;
    }
    __syncthreads();
    float inv = 1.0f / fmaxf(total, 1e-12f);
    float* row = res + ((size_t)b * N_ + i) * N_;
#pragma unroll
    for (int t = 0; t < 4; t++) row[threadIdx.x + t * 256] = v[t] * inv;
}

// =================================================================================
extern "C" void kernel_launch(void* const* d_in, const int* in_sizes, int n_in,
                              void* d_out, int out_size) {
    const float* shots = (const float*)d_in[0];
    const float* node  = (const float*)d_in[1];
    // d_in[2] = 'a' (unused by reference)
    const float* gcn_w = (const float*)d_in[3];
    const float* w_ih  = (const float*)d_in[4];
    const float* w_hh  = (const float*)d_in[5];
    const float* b_ih  = (const float*)d_in[6];
    const float* b_hh  = (const float*)d_in[7];
    const float* f1_w  = (const float*)d_in[8];
    const float* f1_b  = (const float*)d_in[9];
    const float* f2_w  = (const float*)d_in[10];
    const float* f2_b  = (const float*)d_in[11];
    float* res = (float*)d_out;

    k_init<<<1, B_ * H_>>>();                      // launch #1 (independent)
    k_deg<<<BW_ * N_ / 8, 256>>>(shots);           // #2
    k_P<<<BW_ * N_ / 8, 256>>>(node, gcn_w);       // #3
    k_gcn<<<dim3(BW_ * 8, KQ_), 64>>>(shots);      // #4  <- ncu sample lands here
    k_xfin<<<BW_ * N_ * FOUT_ / 4 / 256, 256>>>();
    k_gates<<<dim3(8, KC_), 192>>>(w_ih);
    k_greduce<<<BW_ * 4 * H_ / 256, 256>>>(b_ih, b_hh);
    k_lstm<<<dim3(8, B_), 32>>>(w_hh);
    k_out<<<D_ / 8, 256>>>(f1_w, f1_b);
    k_s<<<B_ * N_ / 256, 256>>>(f2_w);
    k_final<<<B_ * N_, 256>>>(res, f2_b);
}

// round 7
// speedup vs baseline: 1.2025x; 1.0203x over previous
#include <cuda_runtime.h>

// Problem constants
static constexpr int B_   = 4;
static constexpr int W_   = 12;
static constexpr int N_   = 1024;
static constexpr int FIN_ = 32;
static constexpr int FOUT_= 32;
static constexpr int H_   = 256;
static constexpr int BW_  = B_ * W_;        // 48
static constexpr int D_   = N_ * FOUT_;     // 32768
static constexpr int KC_  = 128;            // split-K chunks for gates GEMM (k=256 each)
static constexpr int KQ_  = 8;              // split-K for gcn GEMM (k=128 each)

// ---------------- packed f32x2 helpers ----------------
#define FMA2(acc, a, b) asm("fma.rn.f32x2 %0, %1, %2, %0;" : "+l"(acc) : "l"(a), "l"(b))
#define PACK2(d, f)     asm("mov.b64 %0, {%1, %1};" : "=l"(d) : "f"(f))
#define UNPACK2(lo, hi, d) asm("mov.b64 {%0, %1}, %2;" : "=f"(lo), "=f"(hi) : "l"(d))

// ---------------- scratch (static device globals; no allocation) ----------------
__device__ float g_deg[BW_ * N_];
__device__ float g_P[(size_t)BW_ * N_ * FOUT_];
__device__ float g_xpart[(size_t)KQ_ * BW_ * N_ * FOUT_];   // gcn split-K partials
__device__ float g_X[(size_t)BW_ * D_];                     // [wb = w*B+b][D]
__device__ float g_part[(size_t)KC_ * BW_ * 4 * H_];        // gates split-K partials
__device__ float g_gates[BW_ * 4 * H_];
__device__ float g_h[2][B_ * H_];
__device__ float g_out[B_ * D_];
__device__ float g_s1[B_ * N_];
__device__ float g_s2[B_ * N_];
__device__ int   g_barrier;

// ---------------- init h0 + barrier ----------------------------------------------
__global__ void k_init() {
    int t = threadIdx.x;
    g_h[0][t] = 0.f;
    if (t == 0) g_barrier = 0;
}

// ---------------- K1: fused degree + P -------------------------------------------
// one warp per row; d = (1+rowsum(shots))^-1/2; P[m,o] = d*(node[m,:]@gcn_w[w])[o]
__global__ void k_degP(const float* __restrict__ shots, const float* __restrict__ node,
                       const float* __restrict__ gcn_w) {
    __shared__ float gw[FIN_ * FOUT_];
    int r0 = blockIdx.x * 8;
    int w  = (r0 / N_) % W_;            // rows bw-major: bw = b*W + w
    for (int i = threadIdx.x; i < FIN_ * FOUT_; i += 256)
        gw[i] = gcn_w[(size_t)w * FIN_ * FOUT_ + i];
    __syncthreads();
    int warp = threadIdx.x >> 5, lane = threadIdx.x & 31;
    int r = r0 + warp;
    const float4* p = (const float4*)(shots + (size_t)r * N_);
    float s = 0.f;
#pragma unroll
    for (int i = 0; i < 8; i++) {
        float4 v = p[lane + 32 * i];
        s += v.x + v.y + v.z + v.w;
    }
#pragma unroll
    for (int o = 16; o; o >>= 1) s += __shfl_xor_sync(0xffffffffu, s, o);
    float d = 1.0f / sqrtf(1.0f + s);       // all lanes
    if (lane == 0) g_deg[r] = d;

    float nv = node[(size_t)r * FIN_ + lane];
    float acc = 0.f;
#pragma unroll
    for (int f = 0; f < FIN_; f++) {
        float x = __shfl_sync(0xffffffffu, nv, f);
        acc += x * gw[f * FOUT_ + lane];
    }
    g_P[(size_t)r * FOUT_ + lane] = d * acc;
}

// ---------------- K3: xpart[kq] = shots[n, kq-chunk] @ P[kq-chunk, :] ----------
// 64 threads, tile 128 rows x 32 cols, thread tile 8x8, f32x2 inner loop.
// Grid = (48 bw * 8 row-tiles, KQ_=8 k-chunks of 128).
static constexpr int AS_ = 292;   // A_shT row stride (floats)
__global__ __launch_bounds__(64) void k_gcn(const float* __restrict__ shots) {
    __shared__ __align__(16) float AT[16 * AS_];   // [kk][f(row)]
    __shared__ __align__(16) float PS[16 * 32];    // [kk][col]
    int bw = blockIdx.x >> 3;
    int n0 = (blockIdx.x & 7) << 7;      // * 128
    int kq = blockIdx.y;
    int t = threadIdx.x;
    int tx = t & 3;          // col group (8 cols each)
    int ty = t >> 2;         // row group (8 rows each), 0..15
    const float* Abase = shots + (size_t)bw * N_ * N_;
    const float* Pbase = g_P + (size_t)bw * N_ * FOUT_;

    unsigned long long acc[4][8];
#pragma unroll
    for (int i = 0; i < 4; i++)
#pragma unroll
        for (int j = 0; j < 8; j++) acc[i][j] = 0ull;

    const int r8 = ty * 8;
    const int fr = r8 + ((r8 >> 5) << 2);   // bank-spread row index

    for (int k0 = kq * 128; k0 < kq * 128 + 128; k0 += 16) {
#pragma unroll
        for (int i = 0; i < 8; i++) {
            int idx = t + 64 * i;
            int rr = idx >> 2, q = idx & 3;
            float4 v = *(const float4*)(Abase + (size_t)(n0 + rr) * N_ + k0 + 4 * q);
            int f = rr + ((rr >> 5) << 2);
            AT[(4 * q + 0) * AS_ + f] = v.x;
            AT[(4 * q + 1) * AS_ + f] = v.y;
            AT[(4 * q + 2) * AS_ + f] = v.z;
            AT[(4 * q + 3) * AS_ + f] = v.w;
        }
#pragma unroll
        for (int i = 0; i < 2; i++) {
            int idx = t + 64 * i;
            int kk = idx >> 3, c = idx & 7;
            *(float4*)&PS[kk * 32 + 4 * c] =
                *(const float4*)(Pbase + (size_t)(k0 + kk) * 32 + 4 * c);
        }
        __syncthreads();
#pragma unroll 4
        for (int kk = 0; kk < 16; kk++) {
            ulonglong2 aA = *(const ulonglong2*)&AT[kk * AS_ + fr];
            ulonglong2 aB = *(const ulonglong2*)&AT[kk * AS_ + fr + 4];
            float4 p0 = *(const float4*)&PS[kk * 32 + tx * 8];
            float4 p1 = *(const float4*)&PS[kk * 32 + tx * 8 + 4];
            unsigned long long ap[4];
            ap[0] = aA.x; ap[1] = aA.y; ap[2] = aB.x; ap[3] = aB.y;
            unsigned long long bb[8];
            PACK2(bb[0], p0.x); PACK2(bb[1], p0.y); PACK2(bb[2], p0.z); PACK2(bb[3], p0.w);
            PACK2(bb[4], p1.x); PACK2(bb[5], p1.y); PACK2(bb[6], p1.z); PACK2(bb[7], p1.w);
#pragma unroll
            for (int i = 0; i < 4; i++)
#pragma unroll
                for (int j = 0; j < 8; j++) FMA2(acc[i][j], ap[i], bb[j]);
        }
        __syncthreads();
    }

    float* Xp = g_xpart + (size_t)kq * BW_ * N_ * FOUT_ + (size_t)bw * N_ * FOUT_;
#pragma unroll
    for (int i = 0; i < 4; i++) {
        int ne = n0 + r8 + 2 * i;
        float lo[8], hi[8];
#pragma unroll
        for (int j = 0; j < 8; j++) UNPACK2(lo[j], hi[j], acc[i][j]);
        float4 o0 = {lo[0], lo[1], lo[2], lo[3]};
        float4 o1 = {lo[4], lo[5], lo[6], lo[7]};
        float4 o2 = {hi[0], hi[1], hi[2], hi[3]};
        float4 o3 = {hi[4], hi[5], hi[6], hi[7]};
        *(float4*)(Xp + (size_t)ne * 32 + tx * 8) = o0;
        *(float4*)(Xp + (size_t)ne * 32 + tx * 8 + 4) = o1;
        *(float4*)(Xp + (size_t)(ne + 1) * 32 + tx * 8) = o2;
        *(float4*)(Xp + (size_t)(ne + 1) * 32 + tx * 8 + 4) = o3;
    }
}

// ---------------- K3f: X[n,o] = d[n]*(sum_kq xpart + P[n,o]), time-major --------
__global__ void k_xfin(void) {
    int i4 = blockIdx.x * 256 + threadIdx.x;         // float4 index
    size_t e = (size_t)i4 * 4;
    int bw = (int)(e >> 15);                         // / 32768
    int r  = (int)(e & 32767);
    int n  = r >> 5;
    float4 s = *(const float4*)(g_P + e);
#pragma unroll
    for (int kq = 0; kq < KQ_; kq++) {
        float4 p = *(const float4*)(g_xpart + (size_t)kq * BW_ * N_ * FOUT_ + e);
        s.x += p.x; s.y += p.y; s.z += p.z; s.w += p.w;
    }
    float d = g_deg[bw * N_ + n];
    s.x *= d; s.y *= d; s.z *= d; s.w *= d;
    int w = bw % W_, b = bw / W_;
    *(float4*)(g_X + (size_t)(w * B_ + b) * D_ + r) = s;
}

// ---------------- K4: gates_x = X @ w_ih^T  (wide 8x8 tile, deep split-K) -------
// Block = 48 wb x 256 g over K-chunk 256. 192 threads (6 warps),
// thread tile 8 wb (4 packed pairs) x 8 g (two float4 groups: gl*4, 128+gl*4).
// Grid (4 g-tiles, 128 kc).
static constexpr int XS_  = 52;    // X_shT stride
static constexpr int WS2_ = 260;   // W_shT stride (256 + 4 pad)
__global__ __launch_bounds__(192) void k_gates(const float* __restrict__ w_ih) {
    __shared__ __align__(16) float XT[32 * XS_];    // [kk][wb]   6.7KB
    __shared__ __align__(16) float WT[32 * WS2_];   // [kk][g]   33.3KB
    int g0 = blockIdx.x * 256;
    int kc = blockIdx.y;
    int k0base = kc * 256;
    int t = threadIdx.x;
    int warp = t >> 5, gl = t & 31;
    int wb0 = warp * 8;

    unsigned long long acc[4][8];
#pragma unroll
    for (int i = 0; i < 4; i++)
#pragma unroll
        for (int j = 0; j < 8; j++) acc[i][j] = 0ull;

    for (int s = 0; s < 8; s++) {
        int k0 = k0base + s * 32;
        // stage W: 256 g x 32 k, transposed
        for (int idx = t; idx < 2048; idx += 192) {
            int g = idx >> 3, q = idx & 7;
            float4 v = *(const float4*)(w_ih + (size_t)(g0 + g) * D_ + k0 + 4 * q);
            WT[(4 * q + 0) * WS2_ + g] = v.x;
            WT[(4 * q + 1) * WS2_ + g] = v.y;
            WT[(4 * q + 2) * WS2_ + g] = v.z;
            WT[(4 * q + 3) * WS2_ + g] = v.w;
        }
        // stage X: 48 wb x 32 k, transposed
        for (int idx = t; idx < 384; idx += 192) {
            int wb = idx >> 3, q = idx & 7;
            float4 v = *(const float4*)(g_X + (size_t)wb * D_ + k0 + 4 * q);
            XT[(4 * q + 0) * XS_ + wb] = v.x;
            XT[(4 * q + 1) * XS_ + wb] = v.y;
            XT[(4 * q + 2) * XS_ + wb] = v.z;
            XT[(4 * q + 3) * XS_ + wb] = v.w;
        }
        __syncthreads();
#pragma unroll 4
        for (int kk = 0; kk < 32; kk++) {
            ulonglong2 xA = *(const ulonglong2*)&XT[kk * XS_ + wb0];       // broadcast
            ulonglong2 xB = *(const ulonglong2*)&XT[kk * XS_ + wb0 + 4];
            float4 w0 = *(const float4*)&WT[kk * WS2_ + gl * 4];
            float4 w1 = *(const float4*)&WT[kk * WS2_ + 128 + gl * 4];
            unsigned long long ap[4];
            ap[0] = xA.x; ap[1] = xA.y; ap[2] = xB.x; ap[3] = xB.y;
            unsigned long long b2[8];
            PACK2(b2[0], w0.x); PACK2(b2[1], w0.y); PACK2(b2[2], w0.z); PACK2(b2[3], w0.w);
            PACK2(b2[4], w1.x); PACK2(b2[5], w1.y); PACK2(b2[6], w1.z); PACK2(b2[7], w1.w);
#pragma unroll
            for (int i = 0; i < 4; i++)
#pragma unroll
                for (int j = 0; j < 8; j++) FMA2(acc[i][j], ap[i], b2[j]);
        }
        __syncthreads();
    }
    // epilogue -> split-K partials
#pragma unroll
    for (int i = 0; i < 4; i++) {
#pragma unroll
        for (int j = 0; j < 8; j++) {
            float lo, hi;
            UNPACK2(lo, hi, acc[i][j]);
            int gcol = g0 + ((j < 4) ? (gl * 4 + j) : (128 + gl * 4 + (j - 4)));
            g_part[((size_t)kc * BW_ + wb0 + 2 * i) * 1024 + gcol] = lo;
            g_part[((size_t)kc * BW_ + wb0 + 2 * i + 1) * 1024 + gcol] = hi;
        }
    }
}

// ---------------- K4r: reduce split-K + biases ----------------------------------
__global__ void k_greduce(const float* __restrict__ b_ih, const float* __restrict__ b_hh) {
    int i = blockIdx.x * 256 + threadIdx.x;   // 0..49151
    int g = i & 1023;
    float s = b_ih[g] + b_hh[g];
#pragma unroll 8
    for (int kc = 0; kc < KC_; kc++) s += g_part[(size_t)kc * BW_ * 1024 + i];
    g_gates[i] = s;
}

// ---------------- K5: fused 12-step LSTM (persistent, grid spin-barrier) --------
__global__ void k_lstm(const float* __restrict__ w_hh) {
    __shared__ __align__(16) float hsh[H_];
    int b = blockIdx.y;
    int j = blockIdx.x * 32 + threadIdx.x;
    const float4* wr[4];
#pragma unroll
    for (int r = 0; r < 4; r++) wr[r] = (const float4*)(w_hh + (size_t)(r * H_ + j) * H_);
    float cc = 0.f;

    for (int w = 0; w < W_; w++) {
        int parity = w & 1;
        const float4* hg = (const float4*)(g_h[parity] + b * H_);
#pragma unroll
        for (int i = 0; i < 2; i++) {
            int idx = threadIdx.x + 32 * i;       // float4 index 0..63
            ((float4*)hsh)[idx] = __ldcg(&hg[idx]);
        }
        __syncwarp();

        const float* gx = g_gates + ((size_t)(w * B_ + b)) * 4 * H_;
        float acc[4] = {gx[j], gx[H_ + j], gx[2 * H_ + j], gx[3 * H_ + j]};
        const float4* h4 = (const float4*)hsh;
#pragma unroll 8
        for (int k = 0; k < H_ / 4; k++) {
            float4 hv = h4[k];
#pragma unroll
            for (int r = 0; r < 4; r++) {
                float4 wv = wr[r][k];
                acc[r] += wv.x * hv.x + wv.y * hv.y + wv.z * hv.z + wv.w * hv.w;
            }
        }
        float ig = 1.0f / (1.0f + expf(-acc[0]));
        float fg = 1.0f / (1.0f + expf(-acc[1]));
        float gg = tanhf(acc[2]);
        float og = 1.0f / (1.0f + expf(-acc[3]));
        cc = fg * cc + ig * gg;
        float hv = og * tanhf(cc);
        asm volatile("st.global.cg.f32 [%0], %1;" :: "l"(&g_h[parity ^ 1][b * H_ + j]), "f"(hv));

        __syncwarp();
        if (threadIdx.x == 0) {
            int target = 32 * (w + 1);
            asm volatile("red.release.gpu.global.add.s32 [%0], 1;" :: "l"(&g_barrier));
            int v;
            do {
                asm volatile("ld.acquire.gpu.global.s32 %0, [%1];" : "=r"(v) : "l"(&g_barrier));
            } while (v < target);
        }
        __syncwarp();
    }
}

// ---------------- K6: out[b, r] = hn[b,:]·f1_w[r,:] + f1_b[r] -------------------
__global__ void k_out(const float* __restrict__ f1_w, const float* __restrict__ f1_b) {
    __shared__ __align__(16) float hsh[B_ * H_];
    for (int i = threadIdx.x; i < B_ * H_; i += 256) hsh[i] = g_h[0][i];  // 12 steps -> parity 0
    __syncthreads();
    int warp = threadIdx.x >> 5, lane = threadIdx.x & 31;
    int r = blockIdx.x * 8 + warp;
    const float4* Wr = (const float4*)(f1_w + (size_t)r * H_);
    float a[B_] = {0.f, 0.f, 0.f, 0.f};
#pragma unroll
    for (int t = 0; t < 2; t++) {
        int idx = lane + 32 * t;
        float4 wv = Wr[idx];
#pragma unroll
        for (int b = 0; b < B_; b++) {
            float4 hv = *(const float4*)&hsh[b * H_ + idx * 4];
            a[b] += wv.x * hv.x + wv.y * hv.y + wv.z * hv.z + wv.w * hv.w;
        }
    }
#pragma unroll
    for (int b = 0; b < B_; b++) {
#pragma unroll
        for (int o = 16; o; o >>= 1) a[b] += __shfl_xor_sync(0xffffffffu, a[b], o);
    }
    if (lane == 0) {
        float bb = f1_b[r];
#pragma unroll
        for (int b = 0; b < B_; b++) g_out[(size_t)b * D_ + r] = a[b] + bb;
    }
}

// ---------------- K6c: s1[b,n], s2[b,n] -----------------------------------------
__global__ void k_s(const float* __restrict__ f2_w) {
    int idx = blockIdx.x * 256 + threadIdx.x;  // 0..4095 : b*N + n
    const float4* v4 = (const float4*)(g_out + (size_t)idx * FOUT_);
    const float4* w1 = (const float4*)(f2_w);
    const float4* w2 = (const float4*)(f2_w + FOUT_);
    float s1 = 0.f, s2 = 0.f;
#pragma unroll
    for (int t = 0; t < 8; t++) {
        float4 v = v4[t], a = w1[t], b = w2[t];
        s1 += v.x * a.x + v.y * a.y + v.z * a.z + v.w * a.w;
        s2 += v.x * b.x + v.y * b.y + v.z * b.z + v.w * b.w;
    }
    g_s1[idx] = s1;
    g_s2[idx] = s2;
}

// ---------------- K7: scores, keep mask, L1 row-normalize, write output ----------
__global__ void k_final(float* __restrict__ res, const float* __restrict__ f2_b) {
    __shared__ float s1s[N_], s2s[N_];
    __shared__ float wsum[8];
    __shared__ float total;
    int b = blockIdx.x >> 10;
    int i = blockIdx.x & 1023;
    for (int t = threadIdx.x; t < N_; t += 256) {
        s1s[t] = g_s1[b * N_ + t];
        s2s[t] = g_s2[b * N_ + t];
    }
    __syncthreads();
    float bias = f2_b[0];
    float s1i = s1s[i], s2i = s2s[i];
    float v[4];
    float asum = 0.f;
#pragma unroll
    for (int t = 0; t < 4; t++) {
        int j = threadIdx.x + t * 256;
        float sc = s1i + s2s[j] + bias;
        float st = s1s[j] + s2i + bias;
        float val;
        if (i == j) {
            val = sc;
        } else {
            bool keep = (i < j) ? (sc >= st && sc > 0.f) : (sc > st && sc >= 0.f);
            val = keep ? sc : 0.f;
        }
        v[t] = val;
        asum += fabsf(val);
    }
    int warp = threadIdx.x >> 5, lane = threadIdx.x & 31;
#pragma unroll
    for (int o = 16; o; o >>= 1) asum += __shfl_xor_sync(0xffffffffu, asum, o);
    if (lane == 0) wsum[warp] = asum;
    __syncthreads();
    if (threadIdx.x == 0) {
        float s = 0.f;
#pragma unroll
        for (int k = 0; k < 8; k++) s += wsum[k];
        total = s;
    }
    __syncthreads();
    float inv = 1.0f / fmaxf(total, 1e-12f);
    float* row = res + ((size_t)b * N_ + i) * N_;
#pragma unroll
    for (int t = 0; t < 4; t++) row[threadIdx.x + t * 256] = v[t] * inv;
}

// =================================================================================
extern "C" void kernel_launch(void* const* d_in, const int* in_sizes, int n_in,
                              void* d_out, int out_size) {
    const float* shots = (const float*)d_in[0];
    const float* node  = (const float*)d_in[1];
    // d_in[2] = 'a' (unused by reference)
    const float* gcn_w = (const float*)d_in[3];
    const float* w_ih  = (const float*)d_in[4];
    const float* w_hh  = (const float*)d_in[5];
    const float* b_ih  = (const float*)d_in[6];
    const float* b_hh  = (const float*)d_in[7];
    const float* f1_w  = (const float*)d_in[8];
    const float* f1_b  = (const float*)d_in[9];
    const float* f2_w  = (const float*)d_in[10];
    const float* f2_b  = (const float*)d_in[11];
    float* res = (float*)d_out;

    k_degP<<<BW_ * N_ / 8, 256>>>(shots, node, gcn_w);   // #1 (deg + P fused)
    k_gcn<<<dim3(BW_ * 8, KQ_), 64>>>(shots);            // #2
    k_xfin<<<BW_ * N_ * FOUT_ / 4 / 256, 256>>>();       // #3
    k_gates<<<dim3(4, KC_), 192>>>(w_ih);                // #4  <- ncu sample lands here
    k_greduce<<<BW_ * 4 * H_ / 256, 256>>>(b_ih, b_hh);  // #5
    k_init<<<1, B_ * H_>>>();                            // #6
    k_lstm<<<dim3(8, B_), 32>>>(w_hh);                   // #7
    k_out<<<D_ / 8, 256>>>(f1_w, f1_b);
    k_s<<<B_ * N_ / 256, 256>>>(f2_w);
    k_final<<<B_ * N_, 256>>>(res, f2_b);
}

// round 9
// speedup vs baseline: 1.2707x; 1.0567x over previous
#include <cuda_runtime.h>
#include <cstdint>

// Problem constants
static constexpr int B_   = 4;
static constexpr int W_   = 12;
static constexpr int N_   = 1024;
static constexpr int FIN_ = 32;
static constexpr int FOUT_= 32;
static constexpr int H_   = 256;
static constexpr int BW_  = B_ * W_;        // 48
static constexpr int D_   = N_ * FOUT_;     // 32768
static constexpr int KC_  = 64;             // split-K chunks for gates GEMM (k=512 each)
static constexpr int KQ_  = 8;              // split-K for gcn GEMM (k=128 each)

// ---------------- packed f32x2 helpers ----------------
#define FMA2(acc, a, b) asm("fma.rn.f32x2 %0, %1, %2, %0;" : "+l"(acc) : "l"(a), "l"(b))
#define PACK2(d, f)     asm("mov.b64 %0, {%1, %1};" : "=l"(d) : "f"(f))
#define UNPACK2(lo, hi, d) asm("mov.b64 {%0, %1}, %2;" : "=f"(lo), "=f"(hi) : "l"(d))

// ---------------- cp.async helpers ----------------
__device__ __forceinline__ void cp16(uint32_t dst, const void* src) {
    asm volatile("cp.async.cg.shared.global [%0], [%1], 16;" :: "r"(dst), "l"(src));
}
#define CP_COMMIT() asm volatile("cp.async.commit_group;")
#define CP_WAIT1()  asm volatile("cp.async.wait_group 1;")
#define CP_WAIT0()  asm volatile("cp.async.wait_group 0;")

// ---------------- scratch (static device globals; no allocation) ----------------
__device__ float g_deg[BW_ * N_];
__device__ float g_P[(size_t)BW_ * N_ * FOUT_];
__device__ float g_xpart[(size_t)KQ_ * BW_ * N_ * FOUT_];   // gcn split-K partials
__device__ float g_X[(size_t)BW_ * D_];                     // [wb = w*B+b][D]
__device__ float g_part[(size_t)KC_ * BW_ * 4 * H_];        // gates split-K partials
__device__ float g_gates[BW_ * 4 * H_];
__device__ float g_h[2][B_ * H_];
__device__ float g_out[B_ * D_];
__device__ float g_s1[B_ * N_];
__device__ float g_s2[B_ * N_];
__device__ int   g_barrier;

// ---------------- init h0 + barrier ----------------------------------------------
__global__ void k_init() {
    int t = threadIdx.x;
    g_h[0][t] = 0.f;
    if (t == 0) g_barrier = 0;
}

// ---------------- K1: fused degree + P -------------------------------------------
__global__ void k_degP(const float* __restrict__ shots, const float* __restrict__ node,
                       const float* __restrict__ gcn_w) {
    __shared__ float gw[FIN_ * FOUT_];
    int r0 = blockIdx.x * 8;
    int w  = (r0 / N_) % W_;            // rows bw-major: bw = b*W + w
    for (int i = threadIdx.x; i < FIN_ * FOUT_; i += 256)
        gw[i] = gcn_w[(size_t)w * FIN_ * FOUT_ + i];
    __syncthreads();
    int warp = threadIdx.x >> 5, lane = threadIdx.x & 31;
    int r = r0 + warp;
    const float4* p = (const float4*)(shots + (size_t)r * N_);
    float s = 0.f;
#pragma unroll
    for (int i = 0; i < 8; i++) {
        float4 v = p[lane + 32 * i];
        s += v.x + v.y + v.z + v.w;
    }
#pragma unroll
    for (int o = 16; o; o >>= 1) s += __shfl_xor_sync(0xffffffffu, s, o);
    float d = 1.0f / sqrtf(1.0f + s);
    if (lane == 0) g_deg[r] = d;

    float nv = node[(size_t)r * FIN_ + lane];
    float acc = 0.f;
#pragma unroll
    for (int f = 0; f < FIN_; f++) {
        float x = __shfl_sync(0xffffffffu, nv, f);
        acc += x * gw[f * FOUT_ + lane];
    }
    g_P[(size_t)r * FOUT_ + lane] = d * acc;
}

// ---------------- K3: xpart[kq] = shots[n, kq-chunk] @ P[kq-chunk, :] ----------
static constexpr int AS_ = 292;   // A_shT row stride (floats)
__global__ __launch_bounds__(64) void k_gcn(const float* __restrict__ shots) {
    __shared__ __align__(16) float AT[16 * AS_];   // [kk][f(row)]
    __shared__ __align__(16) float PS[16 * 32];    // [kk][col]
    int bw = blockIdx.x >> 3;
    int n0 = (blockIdx.x & 7) << 7;      // * 128
    int kq = blockIdx.y;
    int t = threadIdx.x;
    int tx = t & 3;
    int ty = t >> 2;
    const float* Abase = shots + (size_t)bw * N_ * N_;
    const float* Pbase = g_P + (size_t)bw * N_ * FOUT_;

    unsigned long long acc[4][8];
#pragma unroll
    for (int i = 0; i < 4; i++)
#pragma unroll
        for (int j = 0; j < 8; j++) acc[i][j] = 0ull;

    const int r8 = ty * 8;
    const int fr = r8 + ((r8 >> 5) << 2);

    for (int k0 = kq * 128; k0 < kq * 128 + 128; k0 += 16) {
#pragma unroll
        for (int i = 0; i < 8; i++) {
            int idx = t + 64 * i;
            int rr = idx >> 2, q = idx & 3;
            float4 v = *(const float4*)(Abase + (size_t)(n0 + rr) * N_ + k0 + 4 * q);
            int f = rr + ((rr >> 5) << 2);
            AT[(4 * q + 0) * AS_ + f] = v.x;
            AT[(4 * q + 1) * AS_ + f] = v.y;
            AT[(4 * q + 2) * AS_ + f] = v.z;
            AT[(4 * q + 3) * AS_ + f] = v.w;
        }
#pragma unroll
        for (int i = 0; i < 2; i++) {
            int idx = t + 64 * i;
            int kk = idx >> 3, c = idx & 7;
            *(float4*)&PS[kk * 32 + 4 * c] =
                *(const float4*)(Pbase + (size_t)(k0 + kk) * 32 + 4 * c);
        }
        __syncthreads();
#pragma unroll 4
        for (int kk = 0; kk < 16; kk++) {
            ulonglong2 aA = *(const ulonglong2*)&AT[kk * AS_ + fr];
            ulonglong2 aB = *(const ulonglong2*)&AT[kk * AS_ + fr + 4];
            float4 p0 = *(const float4*)&PS[kk * 32 + tx * 8];
            float4 p1 = *(const float4*)&PS[kk * 32 + tx * 8 + 4];
            unsigned long long ap[4];
            ap[0] = aA.x; ap[1] = aA.y; ap[2] = aB.x; ap[3] = aB.y;
            unsigned long long bb[8];
            PACK2(bb[0], p0.x); PACK2(bb[1], p0.y); PACK2(bb[2], p0.z); PACK2(bb[3], p0.w);
            PACK2(bb[4], p1.x); PACK2(bb[5], p1.y); PACK2(bb[6], p1.z); PACK2(bb[7], p1.w);
#pragma unroll
            for (int i = 0; i < 4; i++)
#pragma unroll
                for (int j = 0; j < 8; j++) FMA2(acc[i][j], ap[i], bb[j]);
        }
        __syncthreads();
    }

    float* Xp = g_xpart + (size_t)kq * BW_ * N_ * FOUT_ + (size_t)bw * N_ * FOUT_;
#pragma unroll
    for (int i = 0; i < 4; i++) {
        int ne = n0 + r8 + 2 * i;
        float lo[8], hi[8];
#pragma unroll
        for (int j = 0; j < 8; j++) UNPACK2(lo[j], hi[j], acc[i][j]);
        float4 o0 = {lo[0], lo[1], lo[2], lo[3]};
        float4 o1 = {lo[4], lo[5], lo[6], lo[7]};
        float4 o2 = {hi[0], hi[1], hi[2], hi[3]};
        float4 o3 = {hi[4], hi[5], hi[6], hi[7]};
        *(float4*)(Xp + (size_t)ne * 32 + tx * 8) = o0;
        *(float4*)(Xp + (size_t)ne * 32 + tx * 8 + 4) = o1;
        *(float4*)(Xp + (size_t)(ne + 1) * 32 + tx * 8) = o2;
        *(float4*)(Xp + (size_t)(ne + 1) * 32 + tx * 8 + 4) = o3;
    }
}

// ---------------- K3f: X[n,o] = d[n]*(sum_kq xpart + P[n,o]), time-major --------
__global__ void k_xfin(void) {
    int i4 = blockIdx.x * 256 + threadIdx.x;
    size_t e = (size_t)i4 * 4;
    int bw = (int)(e >> 15);
    int r  = (int)(e & 32767);
    int n  = r >> 5;
    float4 s = *(const float4*)(g_P + e);
#pragma unroll
    for (int kq = 0; kq < KQ_; kq++) {
        float4 p = *(const float4*)(g_xpart + (size_t)kq * BW_ * N_ * FOUT_ + e);
        s.x += p.x; s.y += p.y; s.z += p.z; s.w += p.w;
    }
    float d = g_deg[bw * N_ + n];
    s.x *= d; s.y *= d; s.z *= d; s.w *= d;
    int w = bw % W_, b = bw / W_;
    *(float4*)(g_X + (size_t)(w * B_ + b) * D_ + r) = s;
}

// ---------------- K4: gates_x = X @ w_ih^T  (cp.async double-buffered) ----------
// Block = 48 wb x 256 g over K-chunk 512 (16 stages of 32 k). 192 threads.
// Thread tile: 8 wb (4 packed pairs) x 8 g (g = gl + 32j). W in natural [g][k]
// layout (stride 36 floats), staged by cp.async; X transposed [kk][wb] (manual).
static constexpr int WROW_ = 36;                  // W smem row stride (floats)
static constexpr int WBUF_ = 256 * WROW_;         // 9216 floats per buffer
static constexpr int XS_   = 52;                  // XT row stride
static constexpr int XBUF_ = 32 * XS_;            // 1664 floats per buffer
static constexpr int GATES_SMEM = (2 * WBUF_ + 2 * XBUF_) * 4;   // 87040 B

__global__ __launch_bounds__(192) void k_gates(const float* __restrict__ w_ih) {
    extern __shared__ __align__(16) float sm[];
    float* WS = sm;                 // [2][256][36]
    float* XT = sm + 2 * WBUF_;     // [2][32][52]
    const int g0 = blockIdx.x * 256;
    const int kc = blockIdx.y;
    const int kbase = kc * 512;
    const int t = threadIdx.x;
    const int warp = t >> 5, gl = t & 31;
    const int wb0 = warp * 8;
    const uint32_t ws_smem = (uint32_t)__cvta_generic_to_shared(WS);

    unsigned long long acc[4][8];
#pragma unroll
    for (int i = 0; i < 4; i++)
#pragma unroll
        for (int j = 0; j < 8; j++) acc[i][j] = 0ull;

    // W: 256 rows x 32 k  = 2048 x 16B cp.async
#define STAGE_W(bufi, k0)                                                          \
    do {                                                                           \
        for (int idx = t; idx < 2048; idx += 192) {                                \
            int g = idx >> 3, q = idx & 7;                                         \
            cp16(ws_smem + ((bufi) * WBUF_ + g * WROW_ + 4 * q) * 4,               \
                 w_ih + (size_t)(g0 + g) * D_ + (k0) + 4 * q);                     \
        }                                                                          \
    } while (0)
    // X: 48 wb x 32 k, transposed into XT[kk][wb]
#define STAGE_X(bufi, k0)                                                          \
    do {                                                                           \
        float* XB = XT + (bufi) * XBUF_;                                           \
        for (int idx = t; idx < 384; idx += 192) {                                 \
            int wb = idx >> 3, q = idx & 7;                                        \
            float4 v = *(const float4*)(g_X + (size_t)wb * D_ + (k0) + 4 * q);     \
            XB[(4 * q + 0) * XS_ + wb] = v.x;                                      \
            XB[(4 * q + 1) * XS_ + wb] = v.y;                                      \
            XB[(4 * q + 2) * XS_ + wb] = v.z;                                      \
            XB[(4 * q + 3) * XS_ + wb] = v.w;                                      \
        }                                                                          \
    } while (0)

    // prologue: stage 0 into buffer 0
    STAGE_W(0, kbase);
    CP_COMMIT();
    STAGE_X(0, kbase);

    for (int s = 0; s < 16; s++) {
        int buf = s & 1;
        __syncthreads();   // previous compute done -> other buffer free
        if (s < 15) {
            STAGE_W(buf ^ 1, kbase + 32 * (s + 1));
            CP_COMMIT();
            STAGE_X(buf ^ 1, kbase + 32 * (s + 1));
            CP_WAIT1();    // stage s's W group complete (this thread)
        } else {
            CP_WAIT0();
        }
        __syncthreads();   // all threads' waits + X stores visible
        const float* WB = WS + buf * WBUF_;
        const float* XB = XT + buf * XBUF_;
#pragma unroll
        for (int kkc = 0; kkc < 8; kkc++) {
            float wf[8][4];
#pragma unroll
            for (int j = 0; j < 8; j++) {
                float4 v = *(const float4*)&WB[(gl + 32 * j) * WROW_ + kkc * 4];
                wf[j][0] = v.x; wf[j][1] = v.y; wf[j][2] = v.z; wf[j][3] = v.w;
            }
#pragma unroll
            for (int kk = 0; kk < 4; kk++) {
                int krow = kkc * 4 + kk;
                ulonglong2 xA = *(const ulonglong2*)&XB[krow * XS_ + wb0];
                ulonglong2 xB2 = *(const ulonglong2*)&XB[krow * XS_ + wb0 + 4];
                unsigned long long ap[4];
                ap[0] = xA.x; ap[1] = xA.y; ap[2] = xB2.x; ap[3] = xB2.y;
#pragma unroll
                for (int j = 0; j < 8; j++) {
                    unsigned long long b2;
                    PACK2(b2, wf[j][kk]);
#pragma unroll
                    for (int i = 0; i < 4; i++) FMA2(acc[i][j], ap[i], b2);
                }
            }
        }
    }
#undef STAGE_W
#undef STAGE_X

    // epilogue -> split-K partials
#pragma unroll
    for (int i = 0; i < 4; i++) {
#pragma unroll
        for (int j = 0; j < 8; j++) {
            float lo, hi;
            UNPACK2(lo, hi, acc[i][j]);
            int gcol = g0 + gl + 32 * j;
            g_part[((size_t)kc * BW_ + wb0 + 2 * i) * 1024 + gcol] = lo;
            g_part[((size_t)kc * BW_ + wb0 + 2 * i + 1) * 1024 + gcol] = hi;
        }
    }
}

// ---------------- K4r: reduce split-K + biases ----------------------------------
__global__ void k_greduce(const float* __restrict__ b_ih, const float* __restrict__ b_hh) {
    int i = blockIdx.x * 256 + threadIdx.x;   // 0..49151
    int g = i & 1023;
    float s = b_ih[g] + b_hh[g];
#pragma unroll 8
    for (int kc = 0; kc < KC_; kc++) s += g_part[(size_t)kc * BW_ * 1024 + i];
    g_gates[i] = s;
}

// ---------------- K5: fused 12-step LSTM (persistent, grid spin-barrier) --------
__global__ void k_lstm(const float* __restrict__ w_hh) {
    __shared__ __align__(16) float hsh[H_];
    int b = blockIdx.y;
    int j = blockIdx.x * 32 + threadIdx.x;
    const float4* wr[4];
#pragma unroll
    for (int r = 0; r < 4; r++) wr[r] = (const float4*)(w_hh + (size_t)(r * H_ + j) * H_);
    float cc = 0.f;

    for (int w = 0; w < W_; w++) {
        int parity = w & 1;
        const float4* hg = (const float4*)(g_h[parity] + b * H_);
#pragma unroll
        for (int i = 0; i < 2; i++) {
            int idx = threadIdx.x + 32 * i;
            ((float4*)hsh)[idx] = __ldcg(&hg[idx]);
        }
        __syncwarp();

        const float* gx = g_gates + ((size_t)(w * B_ + b)) * 4 * H_;
        float acc[4] = {gx[j], gx[H_ + j], gx[2 * H_ + j], gx[3 * H_ + j]};
        const float4* h4 = (const float4*)hsh;
#pragma unroll 8
        for (int k = 0; k < H_ / 4; k++) {
            float4 hv = h4[k];
#pragma unroll
            for (int r = 0; r < 4; r++) {
                float4 wv = wr[r][k];
                acc[r] += wv.x * hv.x + wv.y * hv.y + wv.z * hv.z + wv.w * hv.w;
            }
        }
        float ig = 1.0f / (1.0f + expf(-acc[0]));
        float fg = 1.0f / (1.0f + expf(-acc[1]));
        float gg = tanhf(acc[2]);
        float og = 1.0f / (1.0f + expf(-acc[3]));
        cc = fg * cc + ig * gg;
        float hv = og * tanhf(cc);
        asm volatile("st.global.cg.f32 [%0], %1;" :: "l"(&g_h[parity ^ 1][b * H_ + j]), "f"(hv));

        __syncwarp();
        if (threadIdx.x == 0) {
            int target = 32 * (w + 1);
            asm volatile("red.release.gpu.global.add.s32 [%0], 1;" :: "l"(&g_barrier));
            int v;
            do {
                asm volatile("ld.acquire.gpu.global.s32 %0, [%1];" : "=r"(v) : "l"(&g_barrier));
            } while (v < target);
        }
        __syncwarp();
    }
}

// ---------------- K6: out[b, r] = hn[b,:]·f1_w[r,:] + f1_b[r] -------------------
__global__ void k_out(const float* __restrict__ f1_w, const float* __restrict__ f1_b) {
    __shared__ __align__(16) float hsh[B_ * H_];
    for (int i = threadIdx.x; i < B_ * H_; i += 256) hsh[i] = g_h[0][i];
    __syncthreads();
    int warp = threadIdx.x >> 5, lane = threadIdx.x & 31;
    int r = blockIdx.x * 8 + warp;
    const float4* Wr = (const float4*)(f1_w + (size_t)r * H_);
    float a[B_] = {0.f, 0.f, 0.f, 0.f};
#pragma unroll
    for (int t = 0; t < 2; t++) {
        int idx = lane + 32 * t;
        float4 wv = Wr[idx];
#pragma unroll
        for (int b = 0; b < B_; b++) {
            float4 hv = *(const float4*)&hsh[b * H_ + idx * 4];
            a[b] += wv.x * hv.x + wv.y * hv.y + wv.z * hv.z + wv.w * hv.w;
        }
    }
#pragma unroll
    for (int b = 0; b < B_; b++) {
#pragma unroll
        for (int o = 16; o; o >>= 1) a[b] += __shfl_xor_sync(0xffffffffu, a[b], o);
    }
    if (lane == 0) {
        float bb = f1_b[r];
#pragma unroll
        for (int b = 0; b < B_; b++) g_out[(size_t)b * D_ + r] = a[b] + bb;
    }
}

// ---------------- K6c: s1[b,n], s2[b,n] -----------------------------------------
__global__ void k_s(const float* __restrict__ f2_w) {
    int idx = blockIdx.x * 256 + threadIdx.x;
    const float4* v4 = (const float4*)(g_out + (size_t)idx * FOUT_);
    const float4* w1 = (const float4*)(f2_w);
    const float4* w2 = (const float4*)(f2_w + FOUT_);
    float s1 = 0.f, s2 = 0.f;
#pragma unroll
    for (int t = 0; t < 8; t++) {
        float4 v = v4[t], a = w1[t], b = w2[t];
        s1 += v.x * a.x + v.y * a.y + v.z * a.z + v.w * a.w;
        s2 += v.x * b.x + v.y * b.y + v.z * b.z + v.w * b.w;
    }
    g_s1[idx] = s1;
    g_s2[idx] = s2;
}

// ---------------- K7: scores, keep mask, L1 row-normalize, write output ----------
__global__ void k_final(float* __restrict__ res, const float* __restrict__ f2_b) {
    __shared__ float s1s[N_], s2s[N_];
    __shared__ float wsum[8];
    __shared__ float total;
    int b = blockIdx.x >> 10;
    int i = blockIdx.x & 1023;
    for (int t = threadIdx.x; t < N_; t += 256) {
        s1s[t] = g_s1[b * N_ + t];
        s2s[t] = g_s2[b * N_ + t];
    }
    __syncthreads();
    float bias = f2_b[0];
    float s1i = s1s[i], s2i = s2s[i];
    float v[4];
    float asum = 0.f;
#pragma unroll
    for (int t = 0; t < 4; t++) {
        int j = threadIdx.x + t * 256;
        float sc = s1i + s2s[j] + bias;
        float st = s1s[j] + s2i + bias;
        float val;
        if (i == j) {
            val = sc;
        } else {
            bool keep = (i < j) ? (sc >= st && sc > 0.f) : (sc > st && sc >= 0.f);
            val = keep ? sc : 0.f;
        }
        v[t] = val;
        asum += fabsf(val);
    }
    int warp = threadIdx.x >> 5, lane = threadIdx.x & 31;
#pragma unroll
    for (int o = 16; o; o >>= 1) asum += __shfl_xor_sync(0xffffffffu, asum, o);
    if (lane == 0) wsum[warp] = asum;
    __syncthreads();
    if (threadIdx.x == 0) {
        float s = 0.f;
#pragma unroll
        for (int k = 0; k < 8; k++) s += wsum[k];
        total = s;
    }
    __syncthreads();
    float inv = 1.0f / fmaxf(total, 1e-12f);
    float* row = res + ((size_t)b * N_ + i) * N_;
#pragma unroll
    for (int t = 0; t < 4; t++) row[threadIdx.x + t * 256] = v[t] * inv;
}

// =================================================================================
extern "C" void kernel_launch(void* const* d_in, const int* in_sizes, int n_in,
                              void* d_out, int out_size) {
    const float* shots = (const float*)d_in[0];
    const float* node  = (const float*)d_in[1];
    // d_in[2] = 'a' (unused by reference)
    const float* gcn_w = (const float*)d_in[3];
    const float* w_ih  = (const float*)d_in[4];
    const float* w_hh  = (const float*)d_in[5];
    const float* b_ih  = (const float*)d_in[6];
    const float* b_hh  = (const float*)d_in[7];
    const float* f1_w  = (const float*)d_in[8];
    const float* f1_b  = (const float*)d_in[9];
    const float* f2_w  = (const float*)d_in[10];
    const float* f2_b  = (const float*)d_in[11];
    float* res = (float*)d_out;

    cudaFuncSetAttribute(k_gates, cudaFuncAttributeMaxDynamicSharedMemorySize, GATES_SMEM);

    k_degP<<<BW_ * N_ / 8, 256>>>(shots, node, gcn_w);   // #1
    k_gcn<<<dim3(BW_ * 8, KQ_), 64>>>(shots);            // #2
    k_xfin<<<BW_ * N_ * FOUT_ / 4 / 256, 256>>>();       // #3
    k_gates<<<dim3(4, KC_), 192, GATES_SMEM>>>(w_ih);    // #4  <- ncu sample slot
    k_greduce<<<BW_ * 4 * H_ / 256, 256>>>(b_ih, b_hh);  // #5
    k_init<<<1, B_ * H_>>>();                            // #6
    k_lstm<<<dim3(8, B_), 32>>>(w_hh);                   // #7
    k_out<<<D_ / 8, 256>>>(f1_w, f1_b);
    k_s<<<B_ * N_ / 256, 256>>>(f2_w);
    k_final<<<B_ * N_, 256>>>(res, f2_b);
}